// round 11
// baseline (speedup 1.0000x reference)
#include <cuda_runtime.h>
#include <cuda_bf16.h>
#include <cuda_fp16.h>
#include <math.h>

// Problem constants
#define BATCH 8192
#define NEXP 16
#define DIM 128
#define UNITS 256
#define FEAT 256
#define NGATE 4
#define TOPK 6
#define LEAKY 0.2f

// ---------------------------------------------------------------------------
// Scratch (device globals — no allocation allowed)
// ---------------------------------------------------------------------------
__device__ __half g_eoh[(size_t)NEXP * BATCH * UNITS];             // [E, B, U] fp16 scratch
__device__ int   g_tki[BATCH * NGATE * TOPK];
__device__ float g_tkw[BATCH * NGATE * TOPK];
__device__ __align__(16) __nv_bfloat16 g_wthi[NEXP * UNITS * DIM]; // [E, N=256, K=128]
__device__ __align__(16) __nv_bfloat16 g_wtlo[NEXP * UNITS * DIM];
__device__ __align__(16) __nv_bfloat16 g_xhi[(size_t)BATCH * 2048]; // X hi, [B, E*D]
__device__ __align__(16) __nv_bfloat16 g_xlo[(size_t)BATCH * 2048]; // X lo residual

// ---------------------------------------------------------------------------
// helpers
// ---------------------------------------------------------------------------
__device__ __forceinline__ unsigned smem_u32(const void* p) {
    unsigned a;
    asm("{ .reg .u64 t; cvta.to.shared.u64 t, %1; cvt.u32.u64 %0, t; }" : "=r"(a) : "l"(p));
    return a;
}

#define SMEM_SWZ(off) ((off) ^ (((off) >> 3) & 0x70))

#define CP_ASYNC16(dst, src) \
    asm volatile("cp.async.cg.shared.global [%0], [%1], 16;" :: "r"(dst), "l"(src))
#define CP_COMMIT() asm volatile("cp.async.commit_group;" ::: "memory")
#define CP_WAIT0()  asm volatile("cp.async.wait_group 0;" ::: "memory")

__device__ __forceinline__ void ldsm4(unsigned* r, unsigned addr) {
    asm volatile("ldmatrix.sync.aligned.m8n8.x4.shared.b16 {%0,%1,%2,%3}, [%4];"
        : "=r"(r[0]), "=r"(r[1]), "=r"(r[2]), "=r"(r[3]) : "r"(addr));
}

__device__ __forceinline__ void mma_bf16(float* d, const unsigned* a, const unsigned* b) {
    asm volatile("mma.sync.aligned.m16n8k16.row.col.f32.bf16.bf16.f32 "
        "{%0,%1,%2,%3}, {%4,%5,%6,%7}, {%8,%9}, {%0,%1,%2,%3};"
        : "+f"(d[0]), "+f"(d[1]), "+f"(d[2]), "+f"(d[3])
        : "r"(a[0]), "r"(a[1]), "r"(a[2]), "r"(a[3]), "r"(b[0]), "r"(b[1]));
}

// pack two floats into bf16x2 hi word and residual-lo word
__device__ __forceinline__ void cvt_hilo(float a, float b, unsigned& hi, unsigned& lo) {
    __nv_bfloat16 ha = __float2bfloat16_rn(a), hb = __float2bfloat16_rn(b);
    hi = ((unsigned)__bfloat16_as_ushort(hb) << 16) | (unsigned)__bfloat16_as_ushort(ha);
    float ra = a - __bfloat162float(ha), rb = b - __bfloat162float(hb);
    __nv_bfloat16 la = __float2bfloat16_rn(ra), lb = __float2bfloat16_rn(rb);
    lo = ((unsigned)__bfloat16_as_ushort(lb) << 16) | (unsigned)__bfloat16_as_ushort(la);
}

// ---------------------------------------------------------------------------
// K0: transpose + split expert weights  W[e][k][n] fp32 -> Wt hi/lo [e][n][k] bf16
// ---------------------------------------------------------------------------
__global__ void __launch_bounds__(256) k0_wt(const float* __restrict__ W)
{
    __shared__ float s[64][68];
    const int e  = blockIdx.z;
    const int k0 = blockIdx.y * 64;
    const int n0 = blockIdx.x * 64;
    const int tid = threadIdx.x;
    const float* Wb = W + (size_t)e * 32768 + (size_t)k0 * 256 + n0;

    for (int i = tid; i < 1024; i += 256) {
        int r = i >> 4, c = i & 15;
        float4 v = *reinterpret_cast<const float4*>(Wb + (size_t)r * 256 + c * 4);
        s[r][c * 4 + 0] = v.x; s[r][c * 4 + 1] = v.y;
        s[r][c * 4 + 2] = v.z; s[r][c * 4 + 3] = v.w;
    }
    __syncthreads();
    for (int u = tid; u < 1024; u += 256) {
        int n = u >> 4, kq = u & 15;
        float x0 = s[kq * 4 + 0][n], x1 = s[kq * 4 + 1][n];
        float x2 = s[kq * 4 + 2][n], x3 = s[kq * 4 + 3][n];
        unsigned h0, l0, h1, l1;
        cvt_hilo(x0, x1, h0, l0);
        cvt_hilo(x2, x3, h1, l1);
        size_t ob = ((size_t)(e * 256) + n0 + n) * 128 + k0 + kq * 4;
        *reinterpret_cast<uint2*>(g_wthi + ob) = make_uint2(h0, h1);
        *reinterpret_cast<uint2*>(g_wtlo + ob) = make_uint2(l0, l1);
    }
}

// ---------------------------------------------------------------------------
// K0x: split X fp32 -> bf16 hi/lo planes (same [B, 2048] layout).
// grid = 8192 (one row per block), 256 threads, 8 elements/thread.
// ---------------------------------------------------------------------------
__global__ void __launch_bounds__(256) k0x_split(const float* __restrict__ X)
{
    const int row = blockIdx.x;
    const int t = threadIdx.x;
    const float4* src = reinterpret_cast<const float4*>(X + (size_t)row * 2048) + t * 2;
    float4 v0 = src[0], v1 = src[1];
    unsigned h0, l0, h1, l1, h2, l2, h3, l3;
    cvt_hilo(v0.x, v0.y, h0, l0);
    cvt_hilo(v0.z, v0.w, h1, l1);
    cvt_hilo(v1.x, v1.y, h2, l2);
    cvt_hilo(v1.z, v1.w, h3, l3);
    size_t ob = (size_t)row * 2048 + t * 8;
    *reinterpret_cast<uint4*>(g_xhi + ob) = make_uint4(h0, h1, h2, h3);
    *reinterpret_cast<uint4*>(g_xlo + ob) = make_uint4(l0, l1, l2, l3);
}

// ---------------------------------------------------------------------------
// K1: gating GEMV + sharp softmax + stable top-6 + weight softmax
// block = 256 threads = 64 rows x 4 gates. grid = 128. Weights-only smem
// (65.7 KB -> 2 CTAs/SM); features streamed via prefetched LDG.128.
// ---------------------------------------------------------------------------
__global__ void __launch_bounds__(256) k1_gating(
    const float* __restrict__ feat, const float* __restrict__ gk,
    const float* __restrict__ gb, const float* __restrict__ gwt)
{
    extern __shared__ float swt[];        // 4 * 4104 floats

    const int tid = threadIdx.x;
    for (int i = tid; i < 4 * 4096; i += 256)
        swt[(i >> 12) * 4104 + (i & 4095)] = gk[i];
    __syncthreads();

    const int g = tid & 3;
    const int r = tid >> 2;               // 0..63
    const int b = blockIdx.x * 64 + r;

    float acc[16];
#pragma unroll
    for (int e = 0; e < 16; e++) acc[e] = 0.f;

    const float* wbase = swt + g * 4104;
    const float4* fr4 = reinterpret_cast<const float4*>(feat + (size_t)b * 256);
    float4 xv = fr4[0];

#pragma unroll 4
    for (int c4 = 0; c4 < 64; c4++) {
        float4 nx = fr4[(c4 + 1) & 63];   // prefetch (wraps harmlessly on last)
        const float xs[4] = {xv.x, xv.y, xv.z, xv.w};
#pragma unroll
        for (int j = 0; j < 4; j++) {
            const float4* wr = reinterpret_cast<const float4*>(wbase + (c4 * 4 + j) * 16);
            float4 w0 = wr[0], w1 = wr[1], w2 = wr[2], w3 = wr[3];
            float x0 = xs[j];
            acc[0]  += x0 * w0.x; acc[1]  += x0 * w0.y; acc[2]  += x0 * w0.z; acc[3]  += x0 * w0.w;
            acc[4]  += x0 * w1.x; acc[5]  += x0 * w1.y; acc[6]  += x0 * w1.z; acc[7]  += x0 * w1.w;
            acc[8]  += x0 * w2.x; acc[9]  += x0 * w2.y; acc[10] += x0 * w2.z; acc[11] += x0 * w2.w;
            acc[12] += x0 * w3.x; acc[13] += x0 * w3.y; acc[14] += x0 * w3.z; acc[15] += x0 * w3.w;
        }
        xv = nx;
    }

    float x[16];
    float m = -1e30f;
#pragma unroll
    for (int e = 0; e < 16; e++) {
        float v = acc[e] + gb[g * 16 + e];
        v = fmaxf(v, 0.f) * gwt[e];
        x[e] = v * 100.f;
        m = fmaxf(m, x[e]);
    }
    float p[16], Z = 0.f;
#pragma unroll
    for (int e = 0; e < 16; e++) { p[e] = expf(x[e] - m); Z += p[e]; }
    float iZ = 1.f / Z;
#pragma unroll
    for (int e = 0; e < 16; e++) p[e] *= iZ;

    unsigned used = 0;
    float tv[TOPK]; int ti[TOPK];
#pragma unroll
    for (int k = 0; k < TOPK; k++) {
        float best = -1.f; int bi = 0;
#pragma unroll
        for (int e = 0; e < 16; e++) {
            bool ok = !((used >> e) & 1u) && (p[e] > best);
            if (ok) { best = p[e]; bi = e; }
        }
        used |= (1u << bi);
        tv[k] = best; ti[k] = bi;
    }
    float m2 = tv[0] * 100.f;
    float wv[TOPK], S = 0.f;
#pragma unroll
    for (int k = 0; k < TOPK; k++) { wv[k] = expf(tv[k] * 100.f - m2); S += wv[k]; }
    float iS = 1.f / S;
    int base = (b * NGATE + g) * TOPK;
#pragma unroll
    for (int k = 0; k < TOPK; k++) { g_tki[base + k] = ti[k]; g_tkw[base + k] = wv[k] * iS; }
}

// ---------------------------------------------------------------------------
// K2: pure bf16 HMMA split GEMM (all operands pre-split in gmem).
// CTA tile M=128, N=128; K in 2 chunks of 64 via cp.async (single 64KB buffer,
// 2 CTAs/SM stagger for load/compute overlap). 8 warps (4m x 2n), warp 32x64.
// Products: AhBh + AlBh + AhBl. Epilogue: bias + LeakyReLU -> fp16 scratch.
// grid = (2 n-tiles, 64 m-tiles, 16 experts).
// ---------------------------------------------------------------------------
#define K2_SMEM 65536

__global__ void __launch_bounds__(256, 2) k2_expert(
    const float* __restrict__ bias)   // [16, 256]
{
    extern __shared__ char smem2[];
    __shared__ float s_bias[128];

    const int tid  = threadIdx.x;
    const int lane = tid & 31;
    const int wid  = tid >> 5;
    const int wm   = wid & 3;        // m quarter (32 rows)
    const int wn   = wid >> 2;       // n half (64 cols)

    const int e  = blockIdx.z;
    const int m0 = blockIdx.y * 128;
    const int n0 = blockIdx.x * 128;

    const unsigned uS = smem_u32(smem2);
    const unsigned uAh = uS, uAl = uS + 16384u, uBh = uS + 32768u, uBl = uS + 49152u;

    if (tid < 128) s_bias[tid] = bias[e * 256 + n0 + tid];

    float acc[2][8][4];
#pragma unroll
    for (int mt = 0; mt < 2; mt++)
#pragma unroll
        for (int nt = 0; nt < 8; nt++)
#pragma unroll
            for (int q = 0; q < 4; q++) acc[mt][nt][q] = 0.f;

    const int a_row = (lane & 7) + ((lane >> 3) & 1) * 8;
    const int a_kh  = (lane >> 4);
    const int b_row = (lane & 7) + ((lane >> 4) & 1) * 8;
    const int b_kh  = ((lane >> 3) & 1);

#pragma unroll
    for (int kc = 0; kc < 2; kc++) {
        // ---- cp.async this k-chunk: A hi/lo [128m][64k], B hi/lo [128n][64k] ----
        {
            const __nv_bfloat16* Ah = g_xhi + (size_t)m0 * 2048 + e * 128 + kc * 64;
            const __nv_bfloat16* Al = g_xlo + (size_t)m0 * 2048 + e * 128 + kc * 64;
            const __nv_bfloat16* Bh = g_wthi + ((size_t)e * 256 + n0) * 128 + kc * 64;
            const __nv_bfloat16* Bl = g_wtlo + ((size_t)e * 256 + n0) * 128 + kc * 64;
#pragma unroll
            for (int j = 0; j < 4; j++) {
                int i = tid + j * 256;          // 1024 chunks of 16B per tile
                int mrow = i >> 3, c8 = i & 7;
                unsigned sw = SMEM_SWZ((unsigned)(mrow * 128 + c8 * 16));
                CP_ASYNC16(uAh + sw, Ah + (size_t)mrow * 2048 + c8 * 8);
                CP_ASYNC16(uAl + sw, Al + (size_t)mrow * 2048 + c8 * 8);
                CP_ASYNC16(uBh + sw, Bh + (size_t)mrow * 128 + c8 * 8);
                CP_ASYNC16(uBl + sw, Bl + (size_t)mrow * 128 + c8 * 8);
            }
            CP_COMMIT();
        }
        CP_WAIT0();
        __syncthreads();

        // ---- 4 k16 steps over this 64-wide chunk ----
#pragma unroll
        for (int ks = 0; ks < 4; ks++) {
            unsigned ah[2][4], al[2][4], bfr[4][4];
#pragma unroll
            for (int mt = 0; mt < 2; mt++) {
                int m = wm * 32 + mt * 16 + a_row;
                unsigned sw = SMEM_SWZ((unsigned)(m * 128 + ks * 32 + a_kh * 16));
                ldsm4(ah[mt], uAh + sw);
                ldsm4(al[mt], uAl + sw);
            }
            // B hi fragments; Ah*Bh + Al*Bh
#pragma unroll
            for (int p = 0; p < 4; p++) {
                int n = wn * 64 + p * 16 + b_row;
                ldsm4(bfr[p], uBh + SMEM_SWZ((unsigned)(n * 128 + ks * 32 + b_kh * 16)));
            }
#pragma unroll
            for (int mt = 0; mt < 2; mt++)
#pragma unroll
                for (int nt = 0; nt < 8; nt++) {
                    const unsigned* bf = &bfr[nt >> 1][(nt & 1) * 2];
                    mma_bf16(acc[mt][nt], ah[mt], bf);
                    mma_bf16(acc[mt][nt], al[mt], bf);
                }
            // B lo fragments; Ah*Bl
#pragma unroll
            for (int p = 0; p < 4; p++) {
                int n = wn * 64 + p * 16 + b_row;
                ldsm4(bfr[p], uBl + SMEM_SWZ((unsigned)(n * 128 + ks * 32 + b_kh * 16)));
            }
#pragma unroll
            for (int mt = 0; mt < 2; mt++)
#pragma unroll
                for (int nt = 0; nt < 8; nt++) {
                    const unsigned* bf = &bfr[nt >> 1][(nt & 1) * 2];
                    mma_bf16(acc[mt][nt], ah[mt], bf);
                }
        }
        if (kc == 0) __syncthreads();    // all reads done before chunk-1 overwrite
    }

    // ---- epilogue: bias + LeakyReLU -> fp16 scratch [E,B,U] ----
    __half* dst = g_eoh + (size_t)e * BATCH * UNITS;
#pragma unroll
    for (int mt = 0; mt < 2; mt++) {
        int mrow = m0 + wm * 32 + mt * 16 + (lane >> 2);
#pragma unroll
        for (int nt = 0; nt < 8; nt++) {
            int nc = wn * 64 + nt * 8 + 2 * (lane & 3);
            float b0 = s_bias[nc], b1 = s_bias[nc + 1];
            float v0 = acc[mt][nt][0] + b0; v0 = (v0 >= 0.f) ? v0 : LEAKY * v0;
            float v1 = acc[mt][nt][1] + b1; v1 = (v1 >= 0.f) ? v1 : LEAKY * v1;
            float v2 = acc[mt][nt][2] + b0; v2 = (v2 >= 0.f) ? v2 : LEAKY * v2;
            float v3 = acc[mt][nt][3] + b1; v3 = (v3 >= 0.f) ? v3 : LEAKY * v3;
            *reinterpret_cast<__half2*>(dst + (size_t)mrow * 256 + n0 + nc) =
                __floats2half2_rn(v0, v1);
            *reinterpret_cast<__half2*>(dst + (size_t)(mrow + 8) * 256 + n0 + nc) =
                __floats2half2_rn(v2, v3);
        }
    }
}

// ---------------------------------------------------------------------------
// K3: transpose-write of expert_outputs [B,U,E] + dense-weight combine.
// Scratch is fp16; outputs fp32.
// ---------------------------------------------------------------------------
__global__ void __launch_bounds__(256) k3_combine(
    float* __restrict__ out1, float* __restrict__ out2)
{
    __shared__ float wd[4][16];

    const int b = blockIdx.x;
    const int u = threadIdx.x;

    if (u < 64) wd[u >> 4][u & 15] = 0.f;
    __syncthreads();
    if (u < NGATE * TOPK) {
        int g = u / TOPK;
        wd[g][g_tki[b * NGATE * TOPK + u]] = g_tkw[b * NGATE * TOPK + u];
    }
    __syncthreads();

    float r[16];
#pragma unroll
    for (int e = 0; e < 16; e++)
        r[e] = __half2float(g_eoh[(size_t)e * BATCH * UNITS + (size_t)b * 256 + u]);

    float4* o2 = reinterpret_cast<float4*>(out2 + ((size_t)b * 256 + u) * 16);
    o2[0] = make_float4(r[0],  r[1],  r[2],  r[3]);
    o2[1] = make_float4(r[4],  r[5],  r[6],  r[7]);
    o2[2] = make_float4(r[8],  r[9],  r[10], r[11]);
    o2[3] = make_float4(r[12], r[13], r[14], r[15]);

#pragma unroll
    for (int g = 0; g < NGATE; g++) {
        float s = 0.f;
#pragma unroll
        for (int e = 0; e < 16; e++)
            s += wd[g][e] * r[e];
        out1[(size_t)b * 1024 + g * 256 + u] = s;
    }
}

// ---------------------------------------------------------------------------
extern "C" void kernel_launch(void* const* d_in, const int* in_sizes, int n_in,
                              void* d_out, int out_size)
{
    const float* inputs = (const float*)d_in[0];
    const float* feat   = (const float*)d_in[1];
    const float* ek     = (const float*)d_in[2];
    const float* eb     = (const float*)d_in[3];
    const float* gk     = (const float*)d_in[4];
    const float* gb     = (const float*)d_in[5];
    const float* gwt    = (const float*)d_in[6];

    float* out  = (float*)d_out;
    float* out1 = out;
    float* out2 = out + (size_t)BATCH * NGATE * UNITS;

    const int k1_smem = 4 * 4104 * (int)sizeof(float);   // 65664
    cudaFuncSetAttribute(k1_gating, cudaFuncAttributeMaxDynamicSharedMemorySize, k1_smem);
    cudaFuncSetAttribute(k2_expert, cudaFuncAttributeMaxDynamicSharedMemorySize, K2_SMEM);

    dim3 g0(4, 2, 16);
    k0_wt<<<g0, 256>>>(ek);

    k0x_split<<<BATCH, 256>>>(inputs);

    k1_gating<<<BATCH / 64, 256, k1_smem>>>(feat, gk, gb, gwt);

    dim3 g2(2, BATCH / 128, NEXP);
    k2_expert<<<g2, 256, K2_SMEM>>>(eb);

    k3_combine<<<BATCH, 256>>>(out1, out2);
}

// round 12
// speedup vs baseline: 1.0020x; 1.0020x over previous
#include <cuda_runtime.h>
#include <cuda_bf16.h>
#include <cuda_fp16.h>
#include <math.h>

// Problem constants
#define BATCH 8192
#define NEXP 16
#define DIM 128
#define UNITS 256
#define FEAT 256
#define NGATE 4
#define TOPK 6
#define LEAKY 0.2f

// ---------------------------------------------------------------------------
// Scratch (device globals — no allocation allowed)
// ---------------------------------------------------------------------------
__device__ __half g_eoh[(size_t)NEXP * BATCH * UNITS];             // [E, B, U] fp16 scratch
__device__ int   g_tki[BATCH * NGATE * TOPK];
__device__ float g_tkw[BATCH * NGATE * TOPK];
__device__ __align__(16) __nv_bfloat16 g_wthi[NEXP * UNITS * DIM]; // [E, N=256, K=128]
__device__ __align__(16) __nv_bfloat16 g_wtlo[NEXP * UNITS * DIM];
__device__ __align__(16) __nv_bfloat16 g_xhi[(size_t)BATCH * 2048]; // X hi, [B, E*D]
__device__ __align__(16) __nv_bfloat16 g_xlo[(size_t)BATCH * 2048]; // X lo residual

// ---------------------------------------------------------------------------
// helpers
// ---------------------------------------------------------------------------
__device__ __forceinline__ unsigned smem_u32(const void* p) {
    unsigned a;
    asm("{ .reg .u64 t; cvta.to.shared.u64 t, %1; cvt.u32.u64 %0, t; }" : "=r"(a) : "l"(p));
    return a;
}

#define SMEM_SWZ(off) ((off) ^ (((off) >> 3) & 0x70))

#define CP_ASYNC16(dst, src) \
    asm volatile("cp.async.cg.shared.global [%0], [%1], 16;" :: "r"(dst), "l"(src))
#define CP_COMMIT() asm volatile("cp.async.commit_group;" ::: "memory")
#define CP_WAIT0()  asm volatile("cp.async.wait_group 0;" ::: "memory")

__device__ __forceinline__ void ldsm4(unsigned* r, unsigned addr) {
    asm volatile("ldmatrix.sync.aligned.m8n8.x4.shared.b16 {%0,%1,%2,%3}, [%4];"
        : "=r"(r[0]), "=r"(r[1]), "=r"(r[2]), "=r"(r[3]) : "r"(addr));
}

__device__ __forceinline__ void mma_bf16(float* d, const unsigned* a, const unsigned* b) {
    asm volatile("mma.sync.aligned.m16n8k16.row.col.f32.bf16.bf16.f32 "
        "{%0,%1,%2,%3}, {%4,%5,%6,%7}, {%8,%9}, {%0,%1,%2,%3};"
        : "+f"(d[0]), "+f"(d[1]), "+f"(d[2]), "+f"(d[3])
        : "r"(a[0]), "r"(a[1]), "r"(a[2]), "r"(a[3]), "r"(b[0]), "r"(b[1]));
}

// pack two floats into bf16x2 hi word and residual-lo word
__device__ __forceinline__ void cvt_hilo(float a, float b, unsigned& hi, unsigned& lo) {
    __nv_bfloat16 ha = __float2bfloat16_rn(a), hb = __float2bfloat16_rn(b);
    hi = ((unsigned)__bfloat16_as_ushort(hb) << 16) | (unsigned)__bfloat16_as_ushort(ha);
    float ra = a - __bfloat162float(ha), rb = b - __bfloat162float(hb);
    __nv_bfloat16 la = __float2bfloat16_rn(ra), lb = __float2bfloat16_rn(rb);
    lo = ((unsigned)__bfloat16_as_ushort(lb) << 16) | (unsigned)__bfloat16_as_ushort(la);
}

// ---------------------------------------------------------------------------
// K0: transpose + split expert weights  W[e][k][n] fp32 -> Wt hi/lo [e][n][k] bf16
// ---------------------------------------------------------------------------
__global__ void __launch_bounds__(256) k0_wt(const float* __restrict__ W)
{
    __shared__ float s[64][68];
    const int e  = blockIdx.z;
    const int k0 = blockIdx.y * 64;
    const int n0 = blockIdx.x * 64;
    const int tid = threadIdx.x;
    const float* Wb = W + (size_t)e * 32768 + (size_t)k0 * 256 + n0;

    for (int i = tid; i < 1024; i += 256) {
        int r = i >> 4, c = i & 15;
        float4 v = *reinterpret_cast<const float4*>(Wb + (size_t)r * 256 + c * 4);
        s[r][c * 4 + 0] = v.x; s[r][c * 4 + 1] = v.y;
        s[r][c * 4 + 2] = v.z; s[r][c * 4 + 3] = v.w;
    }
    __syncthreads();
    for (int u = tid; u < 1024; u += 256) {
        int n = u >> 4, kq = u & 15;
        float x0 = s[kq * 4 + 0][n], x1 = s[kq * 4 + 1][n];
        float x2 = s[kq * 4 + 2][n], x3 = s[kq * 4 + 3][n];
        unsigned h0, l0, h1, l1;
        cvt_hilo(x0, x1, h0, l0);
        cvt_hilo(x2, x3, h1, l1);
        size_t ob = ((size_t)(e * 256) + n0 + n) * 128 + k0 + kq * 4;
        *reinterpret_cast<uint2*>(g_wthi + ob) = make_uint2(h0, h1);
        *reinterpret_cast<uint2*>(g_wtlo + ob) = make_uint2(l0, l1);
    }
}

// ---------------------------------------------------------------------------
// K0x: split X fp32 -> bf16 hi/lo planes (same [B, 2048] layout).
// grid = 8192 (one row per block), 256 threads, 8 elements/thread.
// ---------------------------------------------------------------------------
__global__ void __launch_bounds__(256) k0x_split(const float* __restrict__ X)
{
    const int row = blockIdx.x;
    const int t = threadIdx.x;
    const float4* src = reinterpret_cast<const float4*>(X + (size_t)row * 2048) + t * 2;
    float4 v0 = src[0], v1 = src[1];
    unsigned h0, l0, h1, l1, h2, l2, h3, l3;
    cvt_hilo(v0.x, v0.y, h0, l0);
    cvt_hilo(v0.z, v0.w, h1, l1);
    cvt_hilo(v1.x, v1.y, h2, l2);
    cvt_hilo(v1.z, v1.w, h3, l3);
    size_t ob = (size_t)row * 2048 + t * 8;
    *reinterpret_cast<uint4*>(g_xhi + ob) = make_uint4(h0, h1, h2, h3);
    *reinterpret_cast<uint4*>(g_xlo + ob) = make_uint4(l0, l1, l2, l3);
}

// ---------------------------------------------------------------------------
// K1: gating GEMV + sharp softmax + stable top-6 + weight softmax
// block = 256 threads = 64 rows x 4 gates. grid = 128. Weights-only smem
// (65.7 KB -> 2 CTAs/SM); features streamed via prefetched LDG.128.
// ---------------------------------------------------------------------------
__global__ void __launch_bounds__(256) k1_gating(
    const float* __restrict__ feat, const float* __restrict__ gk,
    const float* __restrict__ gb, const float* __restrict__ gwt)
{
    extern __shared__ float swt[];        // 4 * 4104 floats

    const int tid = threadIdx.x;
    for (int i = tid; i < 4 * 4096; i += 256)
        swt[(i >> 12) * 4104 + (i & 4095)] = gk[i];
    __syncthreads();

    const int g = tid & 3;
    const int r = tid >> 2;               // 0..63
    const int b = blockIdx.x * 64 + r;

    float acc[16];
#pragma unroll
    for (int e = 0; e < 16; e++) acc[e] = 0.f;

    const float* wbase = swt + g * 4104;
    const float4* fr4 = reinterpret_cast<const float4*>(feat + (size_t)b * 256);
    float4 xv = fr4[0];

#pragma unroll 4
    for (int c4 = 0; c4 < 64; c4++) {
        float4 nx = fr4[(c4 + 1) & 63];   // prefetch (wraps harmlessly on last)
        const float xs[4] = {xv.x, xv.y, xv.z, xv.w};
#pragma unroll
        for (int j = 0; j < 4; j++) {
            const float4* wr = reinterpret_cast<const float4*>(wbase + (c4 * 4 + j) * 16);
            float4 w0 = wr[0], w1 = wr[1], w2 = wr[2], w3 = wr[3];
            float x0 = xs[j];
            acc[0]  += x0 * w0.x; acc[1]  += x0 * w0.y; acc[2]  += x0 * w0.z; acc[3]  += x0 * w0.w;
            acc[4]  += x0 * w1.x; acc[5]  += x0 * w1.y; acc[6]  += x0 * w1.z; acc[7]  += x0 * w1.w;
            acc[8]  += x0 * w2.x; acc[9]  += x0 * w2.y; acc[10] += x0 * w2.z; acc[11] += x0 * w2.w;
            acc[12] += x0 * w3.x; acc[13] += x0 * w3.y; acc[14] += x0 * w3.z; acc[15] += x0 * w3.w;
        }
        xv = nx;
    }

    float x[16];
    float m = -1e30f;
#pragma unroll
    for (int e = 0; e < 16; e++) {
        float v = acc[e] + gb[g * 16 + e];
        v = fmaxf(v, 0.f) * gwt[e];
        x[e] = v * 100.f;
        m = fmaxf(m, x[e]);
    }
    float p[16], Z = 0.f;
#pragma unroll
    for (int e = 0; e < 16; e++) { p[e] = expf(x[e] - m); Z += p[e]; }
    float iZ = 1.f / Z;
#pragma unroll
    for (int e = 0; e < 16; e++) p[e] *= iZ;

    unsigned used = 0;
    float tv[TOPK]; int ti[TOPK];
#pragma unroll
    for (int k = 0; k < TOPK; k++) {
        float best = -1.f; int bi = 0;
#pragma unroll
        for (int e = 0; e < 16; e++) {
            bool ok = !((used >> e) & 1u) && (p[e] > best);
            if (ok) { best = p[e]; bi = e; }
        }
        used |= (1u << bi);
        tv[k] = best; ti[k] = bi;
    }
    float m2 = tv[0] * 100.f;
    float wv[TOPK], S = 0.f;
#pragma unroll
    for (int k = 0; k < TOPK; k++) { wv[k] = expf(tv[k] * 100.f - m2); S += wv[k]; }
    float iS = 1.f / S;
    int base = (b * NGATE + g) * TOPK;
#pragma unroll
    for (int k = 0; k < TOPK; k++) { g_tki[base + k] = ti[k]; g_tkw[base + k] = wv[k] * iS; }
}

// ---------------------------------------------------------------------------
// K2: pure bf16 HMMA split GEMM (all operands pre-split in gmem).
// CTA tile M=128, N=128; K in 2 chunks of 64 via cp.async (single 64KB buffer,
// 2 CTAs/SM stagger for load/compute overlap). 8 warps (4m x 2n), warp 32x64.
// Products: AhBh + AlBh + AhBl. Epilogue: bias + LeakyReLU -> fp16 scratch.
// grid = (2 n-tiles, 64 m-tiles, 16 experts).
// ---------------------------------------------------------------------------
#define K2_SMEM 65536

__global__ void __launch_bounds__(256, 2) k2_expert(
    const float* __restrict__ bias)   // [16, 256]
{
    extern __shared__ char smem2[];
    __shared__ float s_bias[128];

    const int tid  = threadIdx.x;
    const int lane = tid & 31;
    const int wid  = tid >> 5;
    const int wm   = wid & 3;        // m quarter (32 rows)
    const int wn   = wid >> 2;       // n half (64 cols)

    const int e  = blockIdx.z;
    const int m0 = blockIdx.y * 128;
    const int n0 = blockIdx.x * 128;

    const unsigned uS = smem_u32(smem2);
    const unsigned uAh = uS, uAl = uS + 16384u, uBh = uS + 32768u, uBl = uS + 49152u;

    if (tid < 128) s_bias[tid] = bias[e * 256 + n0 + tid];

    float acc[2][8][4];
#pragma unroll
    for (int mt = 0; mt < 2; mt++)
#pragma unroll
        for (int nt = 0; nt < 8; nt++)
#pragma unroll
            for (int q = 0; q < 4; q++) acc[mt][nt][q] = 0.f;

    const int a_row = (lane & 7) + ((lane >> 3) & 1) * 8;
    const int a_kh  = (lane >> 4);
    const int b_row = (lane & 7) + ((lane >> 4) & 1) * 8;
    const int b_kh  = ((lane >> 3) & 1);

#pragma unroll
    for (int kc = 0; kc < 2; kc++) {
        // ---- cp.async this k-chunk: A hi/lo [128m][64k], B hi/lo [128n][64k] ----
        {
            const __nv_bfloat16* Ah = g_xhi + (size_t)m0 * 2048 + e * 128 + kc * 64;
            const __nv_bfloat16* Al = g_xlo + (size_t)m0 * 2048 + e * 128 + kc * 64;
            const __nv_bfloat16* Bh = g_wthi + ((size_t)e * 256 + n0) * 128 + kc * 64;
            const __nv_bfloat16* Bl = g_wtlo + ((size_t)e * 256 + n0) * 128 + kc * 64;
#pragma unroll
            for (int j = 0; j < 4; j++) {
                int i = tid + j * 256;          // 1024 chunks of 16B per tile
                int mrow = i >> 3, c8 = i & 7;
                unsigned sw = SMEM_SWZ((unsigned)(mrow * 128 + c8 * 16));
                CP_ASYNC16(uAh + sw, Ah + (size_t)mrow * 2048 + c8 * 8);
                CP_ASYNC16(uAl + sw, Al + (size_t)mrow * 2048 + c8 * 8);
                CP_ASYNC16(uBh + sw, Bh + (size_t)mrow * 128 + c8 * 8);
                CP_ASYNC16(uBl + sw, Bl + (size_t)mrow * 128 + c8 * 8);
            }
            CP_COMMIT();
        }
        CP_WAIT0();
        __syncthreads();

        // ---- 4 k16 steps over this 64-wide chunk ----
#pragma unroll
        for (int ks = 0; ks < 4; ks++) {
            unsigned ah[2][4], al[2][4], bfr[4][4];
#pragma unroll
            for (int mt = 0; mt < 2; mt++) {
                int m = wm * 32 + mt * 16 + a_row;
                unsigned sw = SMEM_SWZ((unsigned)(m * 128 + ks * 32 + a_kh * 16));
                ldsm4(ah[mt], uAh + sw);
                ldsm4(al[mt], uAl + sw);
            }
            // B hi fragments; Ah*Bh + Al*Bh
#pragma unroll
            for (int p = 0; p < 4; p++) {
                int n = wn * 64 + p * 16 + b_row;
                ldsm4(bfr[p], uBh + SMEM_SWZ((unsigned)(n * 128 + ks * 32 + b_kh * 16)));
            }
#pragma unroll
            for (int mt = 0; mt < 2; mt++)
#pragma unroll
                for (int nt = 0; nt < 8; nt++) {
                    const unsigned* bf = &bfr[nt >> 1][(nt & 1) * 2];
                    mma_bf16(acc[mt][nt], ah[mt], bf);
                    mma_bf16(acc[mt][nt], al[mt], bf);
                }
            // B lo fragments; Ah*Bl
#pragma unroll
            for (int p = 0; p < 4; p++) {
                int n = wn * 64 + p * 16 + b_row;
                ldsm4(bfr[p], uBl + SMEM_SWZ((unsigned)(n * 128 + ks * 32 + b_kh * 16)));
            }
#pragma unroll
            for (int mt = 0; mt < 2; mt++)
#pragma unroll
                for (int nt = 0; nt < 8; nt++) {
                    const unsigned* bf = &bfr[nt >> 1][(nt & 1) * 2];
                    mma_bf16(acc[mt][nt], ah[mt], bf);
                }
        }
        if (kc == 0) __syncthreads();    // all reads done before chunk-1 overwrite
    }

    // ---- epilogue: bias + LeakyReLU -> fp16 scratch [E,B,U] ----
    __half* dst = g_eoh + (size_t)e * BATCH * UNITS;
#pragma unroll
    for (int mt = 0; mt < 2; mt++) {
        int mrow = m0 + wm * 32 + mt * 16 + (lane >> 2);
#pragma unroll
        for (int nt = 0; nt < 8; nt++) {
            int nc = wn * 64 + nt * 8 + 2 * (lane & 3);
            float b0 = s_bias[nc], b1 = s_bias[nc + 1];
            float v0 = acc[mt][nt][0] + b0; v0 = (v0 >= 0.f) ? v0 : LEAKY * v0;
            float v1 = acc[mt][nt][1] + b1; v1 = (v1 >= 0.f) ? v1 : LEAKY * v1;
            float v2 = acc[mt][nt][2] + b0; v2 = (v2 >= 0.f) ? v2 : LEAKY * v2;
            float v3 = acc[mt][nt][3] + b1; v3 = (v3 >= 0.f) ? v3 : LEAKY * v3;
            *reinterpret_cast<__half2*>(dst + (size_t)mrow * 256 + n0 + nc) =
                __floats2half2_rn(v0, v1);
            *reinterpret_cast<__half2*>(dst + (size_t)(mrow + 8) * 256 + n0 + nc) =
                __floats2half2_rn(v2, v3);
        }
    }
}

// ---------------------------------------------------------------------------
// K3: transpose-write of expert_outputs [B,U,E] + dense-weight combine.
// Scratch is fp16; outputs fp32.
// ---------------------------------------------------------------------------
__global__ void __launch_bounds__(256) k3_combine(
    float* __restrict__ out1, float* __restrict__ out2)
{
    __shared__ float wd[4][16];

    const int b = blockIdx.x;
    const int u = threadIdx.x;

    if (u < 64) wd[u >> 4][u & 15] = 0.f;
    __syncthreads();
    if (u < NGATE * TOPK) {
        int g = u / TOPK;
        wd[g][g_tki[b * NGATE * TOPK + u]] = g_tkw[b * NGATE * TOPK + u];
    }
    __syncthreads();

    float r[16];
#pragma unroll
    for (int e = 0; e < 16; e++)
        r[e] = __half2float(g_eoh[(size_t)e * BATCH * UNITS + (size_t)b * 256 + u]);

    float4* o2 = reinterpret_cast<float4*>(out2 + ((size_t)b * 256 + u) * 16);
    o2[0] = make_float4(r[0],  r[1],  r[2],  r[3]);
    o2[1] = make_float4(r[4],  r[5],  r[6],  r[7]);
    o2[2] = make_float4(r[8],  r[9],  r[10], r[11]);
    o2[3] = make_float4(r[12], r[13], r[14], r[15]);

#pragma unroll
    for (int g = 0; g < NGATE; g++) {
        float s = 0.f;
#pragma unroll
        for (int e = 0; e < 16; e++)
            s += wd[g][e] * r[e];
        out1[(size_t)b * 1024 + g * 256 + u] = s;
    }
}

// ---------------------------------------------------------------------------
extern "C" void kernel_launch(void* const* d_in, const int* in_sizes, int n_in,
                              void* d_out, int out_size)
{
    const float* inputs = (const float*)d_in[0];
    const float* feat   = (const float*)d_in[1];
    const float* ek     = (const float*)d_in[2];
    const float* eb     = (const float*)d_in[3];
    const float* gk     = (const float*)d_in[4];
    const float* gb     = (const float*)d_in[5];
    const float* gwt    = (const float*)d_in[6];

    float* out  = (float*)d_out;
    float* out1 = out;
    float* out2 = out + (size_t)BATCH * NGATE * UNITS;

    const int k1_smem = 4 * 4104 * (int)sizeof(float);   // 65664
    cudaFuncSetAttribute(k1_gating, cudaFuncAttributeMaxDynamicSharedMemorySize, k1_smem);
    cudaFuncSetAttribute(k2_expert, cudaFuncAttributeMaxDynamicSharedMemorySize, K2_SMEM);

    dim3 g0(4, 2, 16);
    k0_wt<<<g0, 256>>>(ek);

    k0x_split<<<BATCH, 256>>>(inputs);

    k1_gating<<<BATCH / 64, 256, k1_smem>>>(feat, gk, gb, gwt);

    dim3 g2(2, BATCH / 128, NEXP);
    k2_expert<<<g2, 256, K2_SMEM>>>(eb);

    k3_combine<<<BATCH, 256>>>(out1, out2);
}